// round 3
// baseline (speedup 1.0000x reference)
#include <cuda_runtime.h>
#include <cstdint>

// TopologyTracker: 64x64 histogram of (prev, curr) transitions over 16.7M events.
// Output layout (float32): [0..4095] = transitions + counts, [4096] = total + N.
//
// Strategy: the smem atomic ALU floor (2 lanes/cyc/SM) caps a pure-smem
// histogram at ~28us. Split increments across two independent atomic pipes:
//   5/8 events -> per-CTA smem ATOMS
//   3/8 events -> REDG into an L2-resident int scratch (4-way replicated)
// Finalize kernel sums replicas + transitions, writes total, re-zeroes scratch.

#define NUM_TILES 64
#define NUM_BINS  (NUM_TILES * NUM_TILES)   // 4096
#define NREP      4                          // scratch replicas (L2 slice spread)

// Global scratch histogram. Zero-initialized at module load; the finalize
// kernel re-zeroes it every call, so it is always 0 on entry (induction).
__device__ int g_hist[NREP][NUM_BINS];

// ---------------------------------------------------------------------------
// Kernel 1: histogram accumulation.
// ---------------------------------------------------------------------------
__global__ void __launch_bounds__(512, 2)
tt_hist(const int* __restrict__ prev,
        const int* __restrict__ curr,
        int n)
{
    __shared__ int h[NUM_BINS];

    #pragma unroll
    for (int i = threadIdx.x; i < NUM_BINS; i += 512) {
        h[i] = 0;
    }
    __syncthreads();

    int* __restrict__ gh = g_hist[blockIdx.x & (NREP - 1)];

    const int tid    = blockIdx.x * 512 + threadIdx.x;
    const int stride = gridDim.x * 512;

    const int4* __restrict__ p4 = reinterpret_cast<const int4*>(prev);
    const int4* __restrict__ c4 = reinterpret_cast<const int4*>(curr);

    // 8 events per iteration: 4 front-batched 16B streaming loads.
    const int n8 = n >> 3;
    for (int i = tid; i < n8; i += stride) {
        int4 pa = __ldcs(&p4[2 * i]);
        int4 pb = __ldcs(&p4[2 * i + 1]);
        int4 ca = __ldcs(&c4[2 * i]);
        int4 cb = __ldcs(&c4[2 * i + 1]);

        // 5 increments on the smem atomic pipe...
        atomicAdd(&h[(pa.x << 6) + ca.x], 1);
        atomicAdd(&h[(pa.y << 6) + ca.y], 1);
        atomicAdd(&h[(pa.z << 6) + ca.z], 1);
        atomicAdd(&h[(pa.w << 6) + ca.w], 1);
        atomicAdd(&h[(pb.x << 6) + cb.x], 1);
        // ...3 on the L2 REDG pipe (no return value -> RED.E.ADD).
        atomicAdd(&gh[(pb.y << 6) + cb.y], 1);
        atomicAdd(&gh[(pb.z << 6) + cb.z], 1);
        atomicAdd(&gh[(pb.w << 6) + cb.w], 1);
    }

    // Scalar tail (N divisible by 8 in practice; kept for safety).
    for (int i = (n8 << 3) + tid; i < n; i += stride) {
        atomicAdd(&h[(prev[i] << 6) + curr[i]], 1);
    }

    __syncthreads();

    // Flush per-CTA smem histogram into the scratch via REDG.
    #pragma unroll
    for (int i = threadIdx.x; i < NUM_BINS; i += 512) {
        int v = h[i];
        if (v != 0) {
            atomicAdd(&gh[i], v);
        }
    }
}

// ---------------------------------------------------------------------------
// Kernel 2: finalize. out = trans_in + sum(replicas); re-zero scratch;
// write updated total. Exact in float (all values integer-valued < 2^24).
// ---------------------------------------------------------------------------
__global__ void tt_finalize(const float* __restrict__ trans_in,
                            const float* __restrict__ total_in,
                            float* __restrict__ out,
                            int out_size,
                            float n_events)
{
    int i = blockIdx.x * blockDim.x + threadIdx.x;
    if (i < NUM_BINS && i < out_size) {
        int s = 0;
        #pragma unroll
        for (int r = 0; r < NREP; r++) {
            s += g_hist[r][i];
            g_hist[r][i] = 0;
        }
        out[i] = trans_in[i] + (float)s;
    }
    if (i == NUM_BINS && i < out_size) {
        out[NUM_BINS] = total_in[0] + n_events;
    }
}

// ---------------------------------------------------------------------------
// Launcher
// ---------------------------------------------------------------------------
extern "C" void kernel_launch(void* const* d_in, const int* in_sizes, int n_in,
                              void* d_out, int out_size)
{
    const int*   prev     = (const int*)  d_in[0];
    const int*   curr     = (const int*)  d_in[1];
    const float* trans_in = (const float*)d_in[2];
    const float* total_in = (const float*)d_in[3];
    float*       out      = (float*)d_out;

    const int n = in_sizes[0];

    // Histogram accumulation: 2 CTAs/SM * 148 SMs.
    tt_hist<<<296, 512>>>(prev, curr, n);

    // Finalize: 4097 output elements.
    tt_finalize<<<(NUM_BINS + 1 + 511) / 512, 512>>>(trans_in, total_in, out,
                                                     out_size, (float)n);
}